// round 17
// baseline (speedup 1.0000x reference)
#include <cuda_runtime.h>
#include <math.h>

// Problem constants
#define SS 64
#define BB 32
#define DM 586
#define DE 583
#define NL 4
#define K1 17
#define CO1 16
#define CO2 8
#define P2LEN 38
#define CO3 32
#define T3 36
#define NV 128
#define MMW 31      // combined conv1+pool1+conv2+pool2 kernel length
#define XR 592      // smem x row stride (>= 586)
#define NPROD 256   // producer blocks (64 s x 4 quarters)
#define NTAIL 512   // tail blocks (64 s x 8 octants)

// Scratch (no allocations allowed)
__device__ float g_part[SS*4*2];              // per (s, quarter): {sum, sumsq}
__device__ float g_c2part[SS*8*CO2*P2LEN];    // raw superconv partials [s][g][c8][q]
__device__ float g_qsum[4*CO1];               // per-quarter w1 row sums (identical writes)
__device__ unsigned g_scnt[SS];               // producer arrivals per s (monotonic)
__device__ unsigned g_tcnt[SS];               // tail tickets per s (monotonic)

// ---------------------------------------------------------------------------
// Single launch, 768 blocks x 512 threads.
// Producer block (bx<256): (s, qt). Stage w1 slice (8 ci) + w2; gather 8 emb
//   rows (2 warps/row, 10-deep MLP) + per-quarter stats + w1 quarter-sums;
//   build superconv weights W for its 8 ci; superconv partials (g = qt*2+gg)
//   -> g_c2part; release via atomicAdd(g_scnt[s]).
// Tail block (bx>=256): (s, oct). Ticket/epoch spin until its s's 4 producers
//   arrived (monotonic, replay-safe); BN affine fold, o2 assembly, conv3 for
//   4 channels, proj (one vocab row per lane), argmax with first-max rules.
// ---------------------------------------------------------------------------
__global__ void __launch_bounds__(512)
kAll(const int* __restrict__ tokens, const float* __restrict__ emb,
     const float* __restrict__ pos,
     const float* __restrict__ gamma, const float* __restrict__ beta,
     const float* __restrict__ w1, const float* __restrict__ b1,
     const float* __restrict__ w2, const float* __restrict__ b2,
     const float* __restrict__ w3, const float* __restrict__ b3,
     const float* __restrict__ wl, const float* __restrict__ bl,
     float* __restrict__ out) {
    extern __shared__ float dyn[];
    float* xs  = dyn;                    // 8*XR = 4736
    float* sw1 = dyn + 8*XR;             // 2176: [co1][cil*17+k] (this quarter's 8 ci)
    float* sS2 = sw1 + CO1*8*K1;         // 1088
    float* wsl = sS2 + 8*K1*CO2;         // 2048
    __shared__ float sw2s[CO2*CO1];      // 128
    __shared__ float sst[32];
    // tail statics
    __shared__ float o2s[CO2*P2LEN];     // 304
    __shared__ float o3s[4*T3];          // 144
    __shared__ float sa8[CO2], sb8[CO2];
    __shared__ float sAC[2];
    __shared__ float swv[16];
    __shared__ int   swi[16];

    int bx   = blockIdx.x;
    int tid  = threadIdx.x;
    int wid  = tid >> 5;
    int lane = tid & 31;
    const float scale = sqrtf(586.0f);

    if (bx < NPROD) {
        // ==================== producer ====================
        int s  = bx >> 2;
        int qt = bx & 3;

        // stage weights
        for (int i = tid; i < CO1*8*K1; i += 512) {
            int co1 = i / (8*K1);
            int off = i - co1*(8*K1);
            sw1[i] = w1[co1*(BB*K1) + qt*(8*K1) + off];
        }
        if (tid < CO2*CO1) sw2s[tid] = w2[tid];
        __syncthreads();

        // gather 8 rows (2 warps/row) + stats
        {
            int ri   = wid >> 1;
            int part = wid & 1;
            int b    = qt*8 + ri;
            int tok  = tokens[s*BB + b];
            const float* row = emb + (size_t)tok * DE;
            float sum = 0.f, sq = 0.f;
            int dbase = lane + 32*part;
            #pragma unroll
            for (int k = 0; k < 10; k++) {
                int d = dbase + 64*k;
                if (d < DE) {
                    float v = row[d] * scale;
                    xs[ri*XR + d] = v;
                    sum += v; sq += v*v;
                }
            }
            if (part == 0 && lane < 3) {
                float v = pos[(s*BB + b)*3 + lane];
                xs[ri*XR + DE + lane] = v;
                sum += v; sq += v*v;
            }
            #pragma unroll
            for (int off = 16; off >= 1; off >>= 1) {
                sum += __shfl_down_sync(0xffffffffu, sum, off);
                sq  += __shfl_down_sync(0xffffffffu, sq,  off);
            }
            if (lane == 0) { sst[wid] = sum; sst[16 + wid] = sq; }
        }
        __syncthreads();

        // per-quarter w1 sums (warp wid = co1; identical across s: benign race)
        {
            float p = 0.f;
            for (int j = lane; j < 8*K1; j += 32) p += sw1[wid*(8*K1) + j];
            #pragma unroll
            for (int off = 16; off >= 1; off >>= 1)
                p += __shfl_down_sync(0xffffffffu, p, off);
            if (lane == 0) g_qsum[qt*CO1 + wid] = p;
        }
        if (tid == 0) {
            float ts = 0.f, tq = 0.f;
            #pragma unroll
            for (int i = 0; i < 16; i++) { ts += sst[i]; tq += sst[16 + i]; }
            g_part[(s*4 + qt)*2 + 0] = ts;
            g_part[(s*4 + qt)*2 + 1] = tq;
        }

        // S2[(ci*17+k)*8+c8]
        for (int e = tid; e < 8*K1*CO2; e += 512) {
            int c8 = e & 7;
            int t  = e >> 3;
            int k  = t % K1;
            int ci = t / K1;
            float acc = 0.f;
            #pragma unroll
            for (int co1 = 0; co1 < CO1; co1++)
                acc += sw2s[c8*CO1 + co1] * sw1[co1*(8*K1) + ci*K1 + k];
            sS2[(ci*K1 + k)*CO2 + c8] = acc;
        }
        __syncthreads();
        // W[(ci*32+mm)*8+c8]
        for (int e = tid; e < 8*MMW*CO2; e += 512) {
            int c8 = e & 7;
            int t  = e >> 3;
            int mm = t % MMW;
            int ci = t / MMW;
            int dlo = mm - (K1-1); if (dlo < 0) dlo = 0;
            int dhi = mm;          if (dhi > 14) dhi = 14;
            float acc = 0.f;
            for (int d = dlo; d <= dhi; d++)
                acc += sS2[(ci*K1 + (mm - d))*CO2 + c8];
            wsl[(ci*32 + mm)*CO2 + c8] = acc * (1.f/15.f);
        }
        __syncthreads();

        // superconv partials: gg(2) x c8(8) x q(38) = 608 tasks
        for (int t = tid; t < 2*CO2*P2LEN; t += 512) {
            int q  = t % P2LEN;
            int rr = t / P2LEN;
            int c8 = rr & 7;
            int gg = rr >> 3;
            float acc0 = 0.f, acc1 = 0.f;
            const float* xb = xs + (gg*4)*XR + 15*q;
            #pragma unroll
            for (int ci = 0; ci < 4; ci++) {
                const float* xr = xb + ci*XR;
                const float* wp = wsl + (gg*4 + ci)*(32*CO2) + c8;
                #pragma unroll
                for (int mm = 0; mm < MMW; mm += 2) {
                    acc0 += wp[mm*CO2] * xr[mm];
                    if (mm + 1 < MMW) acc1 += wp[(mm+1)*CO2] * xr[mm+1];
                }
            }
            g_c2part[(s*8 + qt*2 + gg)*(CO2*P2LEN) + c8*P2LEN + q] = acc0 + acc1;
        }

        // release
        __threadfence();
        __syncthreads();
        if (tid == 0) atomicAdd(&g_scnt[s], 1u);
        return;
    }

    // ==================== tail ====================
    int tb  = bx - NPROD;
    int s   = tb >> 3;
    int oct = tb & 7;

    if (tid == 0) {
        unsigned t = atomicAdd(&g_tcnt[s], 1u);
        unsigned target = ((t >> 3) + 1u) * 4u;   // epoch-aligned, wrap-safe
        volatile unsigned* vp = &g_scnt[s];
        while ((int)(*vp - target) < 0) { __nanosleep(64); }
        __threadfence();
    }
    __syncthreads();

    // ws2a/ws2b (threads 0..7) and BN affine (thread 8)
    if (tid < CO2) {
        float a = 0.f, bb = 0.f;
        #pragma unroll
        for (int co1 = 0; co1 < CO1; co1++) {
            float wv = w2[tid*CO1 + co1];
            float ws = (__ldcg(&g_qsum[co1])        + __ldcg(&g_qsum[CO1 + co1]))
                     + (__ldcg(&g_qsum[2*CO1 + co1]) + __ldcg(&g_qsum[3*CO1 + co1]));
            a  += wv * ws;
            bb += wv * b1[co1];
        }
        sa8[tid] = a;
        sb8[tid] = bb;
    } else if (tid == 8) {
        float invN = 1.f / (float)(BB*DM);
        float ts = (__ldcg(&g_part[s*8 + 0]) + __ldcg(&g_part[s*8 + 2]))
                 + (__ldcg(&g_part[s*8 + 4]) + __ldcg(&g_part[s*8 + 6]));
        float tq = (__ldcg(&g_part[s*8 + 1]) + __ldcg(&g_part[s*8 + 3]))
                 + (__ldcg(&g_part[s*8 + 5]) + __ldcg(&g_part[s*8 + 7]));
        float m = ts * invN;
        float v = tq * invN - m*m;   // biased var, matches reference
        float A = 1.f, Cf = 0.f;
        #pragma unroll
        for (int l = 0; l < NL; l++) {
            float gg = gamma[l*SS + s];
            float bb = beta[l*SS + s];
            float inv = rsqrtf(v + 1e-5f);
            float a = gg * inv;
            float c = bb - a * m;
            A = a * A;
            Cf = a * Cf + c;
            m = bb;
            v = a * a * v;
        }
        sAC[0] = A; sAC[1] = Cf;
    }
    __syncthreads();

    float A = sAC[0], Cf = sAC[1];
    // o2 assembly: A*(sum of 8 partials) + Cf*ws2a + ws2b + b2
    {
        const float* pp = g_c2part + s*8*(CO2*P2LEN);
        for (int i = tid; i < CO2*P2LEN; i += 512) {
            int c8 = i / P2LEN;
            float p0 = __ldcg(&pp[i]),         p1 = __ldcg(&pp[304 + i]);
            float p2 = __ldcg(&pp[2*304 + i]), p3 = __ldcg(&pp[3*304 + i]);
            float p4 = __ldcg(&pp[4*304 + i]), p5 = __ldcg(&pp[5*304 + i]);
            float p6 = __ldcg(&pp[6*304 + i]), p7 = __ldcg(&pp[7*304 + i]);
            float acc = ((p0 + p1) + (p2 + p3)) + ((p4 + p5) + (p6 + p7));
            o2s[i] = A*acc + Cf*sa8[c8] + sb8[c8] + b2[c8];
        }
    }
    __syncthreads();

    // conv3 for this octant's 4 channels: (8,38) -> (4,36)
    for (int i = tid; i < 4*T3; i += 512) {
        int col = i / T3;
        int co  = oct*4 + col;
        int t   = i - col*T3;
        float acc = b3[co];
        #pragma unroll
        for (int c8 = 0; c8 < CO2; c8++) {
            const float* rr = o2s + c8*P2LEN + t;
            const float* w = w3 + (co*CO2 + c8)*3;
            acc += w[0]*rr[0] + w[1]*rr[1] + w[2]*rr[2];
        }
        o3s[i] = acc;
    }
    __syncthreads();

    // projection + argmax: 16 warps = 4 channels x 4 vocab segments of 32.
    // One vocab row per lane (shortest chains); first-max tie rules kept.
    {
        int c   = wid >> 2;
        int seg = wid & 3;
        int v   = seg*32 + lane;
        float orow[T3];
        #pragma unroll
        for (int k = 0; k < T3; k++) orow[k] = o3s[c*T3 + k];

        const float4* wr = (const float4*)(wl + v*T3);  // 144B rows, 16B-aligned
        float d0 = bl[v], d1 = 0.f;
        #pragma unroll
        for (int k4 = 0; k4 < 9; k4 += 2) {
            float4 w4 = wr[k4];
            d0 += orow[4*k4+0]*w4.x + orow[4*k4+1]*w4.y
                + orow[4*k4+2]*w4.z + orow[4*k4+3]*w4.w;
        }
        #pragma unroll
        for (int k4 = 1; k4 < 9; k4 += 2) {
            float4 w4 = wr[k4];
            d1 += orow[4*k4+0]*w4.x + orow[4*k4+1]*w4.y
                + orow[4*k4+2]*w4.z + orow[4*k4+3]*w4.w;
        }
        float bestv = d0 + d1;
        int   besti = v;
        #pragma unroll
        for (int off = 16; off >= 1; off >>= 1) {
            float ov = __shfl_down_sync(0xffffffffu, bestv, off);
            int   oi = __shfl_down_sync(0xffffffffu, besti, off);
            if (ov > bestv || (ov == bestv && oi < besti)) { bestv = ov; besti = oi; }
        }
        if (lane == 0) { swv[wid] = bestv; swi[wid] = besti; }
    }
    __syncthreads();
    if (tid < 4) {
        float bv = swv[tid*4];
        int   bi = swi[tid*4];
        #pragma unroll
        for (int j = 1; j < 4; j++) {
            float ov = swv[tid*4 + j];
            int   oi = swi[tid*4 + j];
            if (ov > bv || (ov == bv && oi < bi)) { bv = ov; bi = oi; }
        }
        out[s*BB + oct*4 + tid] = (float)bi;
    }
}

// ---------------------------------------------------------------------------
extern "C" void kernel_launch(void* const* d_in, const int* in_sizes, int n_in,
                              void* d_out, int out_size) {
    const int*   tokens = (const int*)  d_in[0];
    const float* emb    = (const float*)d_in[1];
    const float* pos    = (const float*)d_in[2];
    const float* gamma  = (const float*)d_in[3];
    const float* beta   = (const float*)d_in[4];
    const float* w1     = (const float*)d_in[5];
    const float* b1     = (const float*)d_in[6];
    const float* w2     = (const float*)d_in[7];
    const float* b2     = (const float*)d_in[8];
    const float* w3     = (const float*)d_in[9];
    const float* b3     = (const float*)d_in[10];
    const float* wl     = (const float*)d_in[11];
    const float* bl     = (const float*)d_in[12];
    float* out = (float*)d_out;

    size_t sh = (size_t)(8*XR + CO1*8*K1 + 8*K1*CO2 + 8*32*CO2) * sizeof(float); // 40192 B
    cudaFuncSetAttribute(kAll, cudaFuncAttributeMaxDynamicSharedMemorySize, (int)sh);

    kAll<<<NPROD + NTAIL, 512, sh>>>(tokens, emb, pos, gamma, beta, w1, b1,
                                     w2, b2, w3, b3, wl, bl, out);
}